// round 1
// baseline (speedup 1.0000x reference)
#include <cuda_runtime.h>

// S4D SSM layer, exact recurrence formulation of the FFT causal conv.
// y[l,b,d] = silu( Re(sum_n p_n s_n[l]) + x[l,b,d]*Dp[d] ),  s = q*s + x.
//
// 3-pass chunked scan:
//  pass1: per-(chunk,b,d) local scan (zero init) -> end states to g_state
//  pass2: carry propagation across chunks with q^TCHUNK
//  pass3: per-(chunk,b,d) scan with true init + projection + residual + silu

#define NSTATE 16
#define PACKS  8       // 2 states per f32x2 pack
#define TCHUNK 256     // must be power of two (pass2 squares log2(TCHUNK) times)
#define LOG2_TCHUNK 8
#define SCALE_F 0.25f  // sqrt(1/16)

typedef unsigned long long ull;

// f32x2 packed math (Blackwell sm_103a)
__device__ __forceinline__ ull pack2(float lo, float hi) {
    ull r; asm("mov.b64 %0, {%1,%2};" : "=l"(r) : "f"(lo), "f"(hi)); return r;
}
__device__ __forceinline__ void unpack2(ull v, float& a, float& b) {
    asm("mov.b64 {%0,%1}, %2;" : "=f"(a), "=f"(b) : "l"(v));
}
__device__ __forceinline__ ull fma2(ull a, ull b, ull c) {
    ull d; asm("fma.rn.f32x2 %0, %1, %2, %3;" : "=l"(d) : "l"(a), "l"(b), "l"(c)); return d;
}
__device__ __forceinline__ ull mul2(ull a, ull b) {
    ull d; asm("mul.rn.f32x2 %0, %1, %2;" : "=l"(d) : "l"(a), "l"(b)); return d;
}

// chunk-boundary states: layout ((c*BSZ + b)*NSTATE + n)*D + d   (coalesced in d)
__device__ float2 g_state[1 << 21];  // 16 MB scratch, static (allocation-free)

// Compute discretized q_n for feature d (bilinear transform).
__device__ __forceinline__ void compute_q(
    const float* __restrict__ log_dt, const float* __restrict__ log_A_real,
    const float* __restrict__ A_imag, int d,
    float* qr, float* qi, float* dt_out)
{
    float dt = __expf(log_dt[d]);
    *dt_out = dt;
#pragma unroll
    for (int n = 0; n < NSTATE; n++) {
        float zr = -0.5f * dt * __expf(log_A_real[d * NSTATE + n]);
        float zi =  0.5f * dt * A_imag[d * NSTATE + n];
        float omz = 1.0f - zr;
        float inv = __fdividef(1.0f, omz * omz + zi * zi);
        qr[n] = (1.0f - zr * zr - zi * zi) * inv;
        qi[n] = 2.0f * zi * inv;
    }
}

__global__ void __launch_bounds__(128) s4d_pass1(
    const float* __restrict__ x, const float* __restrict__ log_dt,
    const float* __restrict__ log_A_real, const float* __restrict__ A_imag,
    int L, int D)
{
    int d = blockIdx.x * blockDim.x + threadIdx.x;
    if (d >= D) return;
    int b = blockIdx.y;
    int c = blockIdx.z;
    int BSZ = gridDim.y;

    float qr[NSTATE], qi[NSTATE], dt;
    compute_q(log_dt, log_A_real, A_imag, d, qr, qi, &dt);

    ull Qr[PACKS], Qi[PACKS], nQi[PACKS], Sr[PACKS], Sm[PACKS];
#pragma unroll
    for (int j = 0; j < PACKS; j++) {
        Qr[j]  = pack2(qr[2*j],  qr[2*j+1]);
        Qi[j]  = pack2(qi[2*j],  qi[2*j+1]);
        nQi[j] = pack2(-qi[2*j], -qi[2*j+1]);
        Sr[j] = 0ull; Sm[j] = 0ull;   // state; Sm holds m = -si
    }

    int l0 = c * TCHUNK;
    int l1 = min(l0 + TCHUNK, L);
    const float* xp = x + ((long long)l0 * BSZ + b) * D + d;
    int xstride = BSZ * D;

    for (int l = l0; l < l1; l++) {
        float xv = *xp; xp += xstride;
        ull X2 = pack2(xv, xv);
#pragma unroll
        for (int j = 0; j < PACKS; j++) {
            // sr' = qr*sr - qi*si + x  = qr*sr + qi*m + x
            ull t   = fma2(Qi[j], Sm[j], X2);
            ull nsr = fma2(Qr[j], Sr[j], t);
            // m'  = -qi*sr + qr*m
            ull nm  = fma2(nQi[j], Sr[j], mul2(Qr[j], Sm[j]));
            Sr[j] = nsr; Sm[j] = nm;
        }
    }

    float2* st = g_state + (((long long)c * BSZ + b) * NSTATE) * D + d;
#pragma unroll
    for (int j = 0; j < PACKS; j++) {
        float r0, r1, m0, m1;
        unpack2(Sr[j], r0, r1); unpack2(Sm[j], m0, m1);
        st[(2*j    ) * D] = make_float2(r0, -m0);  // store (sr, si)
        st[(2*j + 1) * D] = make_float2(r1, -m1);
    }
}

__global__ void s4d_pass2(
    const float* __restrict__ log_dt, const float* __restrict__ log_A_real,
    const float* __restrict__ A_imag, int D, int BSZ, int NCH)
{
    int id = blockIdx.x * blockDim.x + threadIdx.x;
    int total = BSZ * NSTATE * D;
    if (id >= total) return;
    int d = id % D;
    int n = (id / D) % NSTATE;
    int b = id / (D * NSTATE);

    float dt = __expf(log_dt[d]);
    float zr = -0.5f * dt * __expf(log_A_real[d * NSTATE + n]);
    float zi =  0.5f * dt * A_imag[d * NSTATE + n];
    float omz = 1.0f - zr;
    float inv = __fdividef(1.0f, omz * omz + zi * zi);
    float qr = (1.0f - zr * zr - zi * zi) * inv;
    float qi = 2.0f * zi * inv;

    // q^TCHUNK via repeated squaring (TCHUNK = 2^LOG2_TCHUNK)
#pragma unroll
    for (int i = 0; i < LOG2_TCHUNK; i++) {
        float nr = qr * qr - qi * qi;
        float ni = 2.0f * qr * qi;
        qr = nr; qi = ni;
    }

    long long base    = ((long long)b * NSTATE + n) * D + d;
    long long cstride = (long long)BSZ * NSTATE * D;
    float2 s = g_state[base];
    for (int c = 1; c < NCH; c++) {
        float2 t = g_state[base + (long long)c * cstride];
        float nr = qr * s.x - qi * s.y + t.x;
        float ni = qr * s.y + qi * s.x + t.y;
        s.x = nr; s.y = ni;
        g_state[base + (long long)c * cstride] = s;
    }
}

__global__ void __launch_bounds__(128) s4d_pass3(
    const float* __restrict__ x, const float* __restrict__ log_dt,
    const float* __restrict__ log_A_real, const float* __restrict__ A_imag,
    const float* __restrict__ Bparam, const float* __restrict__ Cparam,
    const float* __restrict__ Dparam, float* __restrict__ out,
    int L, int D)
{
    int d = blockIdx.x * blockDim.x + threadIdx.x;
    if (d >= D) return;
    int b = blockIdx.y;
    int c = blockIdx.z;
    int BSZ = gridDim.y;

    float qr[NSTATE], qi[NSTATE], dt;
    compute_q(log_dt, log_A_real, A_imag, d, qr, qi, &dt);

    ull Qr[PACKS], Qi[PACKS], nQi[PACKS], Pr[PACKS], Pi[PACKS], Sr[PACKS], Sm[PACKS];
#pragma unroll
    for (int j = 0; j < PACKS; j++) {
        float prj[2], pij[2];
#pragma unroll
        for (int k = 0; k < 2; k++) {
            int n = 2 * j + k;
            float zr = -0.5f * dt * __expf(log_A_real[d * NSTATE + n]);
            float zi =  0.5f * dt * A_imag[d * NSTATE + n];
            float omz = 1.0f - zr;
            float inv = __fdividef(1.0f, omz * omz + zi * zi);
            float Br = Bparam[(d * NSTATE + n) * 2 + 0];
            float Bi = Bparam[(d * NSTATE + n) * 2 + 1];
            float Cr = Cparam[(d * NSTATE + n) * 2 + 0];
            float Ci = Cparam[(d * NSTATE + n) * 2 + 1];
            float ccr = Br * Cr - Bi * Ci;
            float cci = Br * Ci + Bi * Cr;
            float w = dt * SCALE_F * inv;
            prj[k] = w * (ccr * omz - cci * zi);
            pij[k] = w * (ccr * zi + cci * omz);
        }
        Qr[j]  = pack2(qr[2*j],  qr[2*j+1]);
        Qi[j]  = pack2(qi[2*j],  qi[2*j+1]);
        nQi[j] = pack2(-qi[2*j], -qi[2*j+1]);
        Pr[j]  = pack2(prj[0], prj[1]);
        Pi[j]  = pack2(pij[0], pij[1]);
        Sr[j] = 0ull; Sm[j] = 0ull;
    }

    // true incoming state = end state of chunk c-1
    if (c > 0) {
        const float2* st = g_state + (((long long)(c - 1) * BSZ + b) * NSTATE) * D + d;
#pragma unroll
        for (int j = 0; j < PACKS; j++) {
            float2 v0 = st[(2*j    ) * D];
            float2 v1 = st[(2*j + 1) * D];
            Sr[j] = pack2(v0.x, v1.x);
            Sm[j] = pack2(-v0.y, -v1.y);  // m = -si
        }
    }

    float dpar = Dparam[d];
    int l0 = c * TCHUNK;
    int l1 = min(l0 + TCHUNK, L);
    const float* xp = x + ((long long)l0 * BSZ + b) * D + d;
    float* op = out + ((long long)l0 * BSZ + b) * D + d;
    int xstride = BSZ * D;

    for (int l = l0; l < l1; l++) {
        float xv = *xp; xp += xstride;
        ull X2 = pack2(xv, xv);
        ull acc0 = 0ull, acc1 = 0ull;
#pragma unroll
        for (int j = 0; j < PACKS; j++) {
            ull t   = fma2(Qi[j], Sm[j], X2);
            ull nsr = fma2(Qr[j], Sr[j], t);
            ull nm  = fma2(nQi[j], Sr[j], mul2(Qr[j], Sm[j]));
            Sr[j] = nsr; Sm[j] = nm;
            // y += pr*sr' + pi*m'   (= pr*sr - pi*si)
            if (j & 1) {
                acc1 = fma2(Pi[j], nm, acc1);
                acc1 = fma2(Pr[j], nsr, acc1);
            } else {
                acc0 = fma2(Pi[j], nm, acc0);
                acc0 = fma2(Pr[j], nsr, acc0);
            }
        }
        float a0, a1, b0, b1;
        unpack2(acc0, a0, a1); unpack2(acc1, b0, b1);
        float y = (a0 + a1) + (b0 + b1);
        float z = fmaf(xv, dpar, y);
        float sg = __fdividef(1.0f, 1.0f + __expf(-z));
        *op = z * sg;
        op += xstride;
    }
}

extern "C" void kernel_launch(void* const* d_in, const int* in_sizes, int n_in,
                              void* d_out, int out_size)
{
    const float* x      = (const float*)d_in[0];
    const float* log_dt = (const float*)d_in[1];
    const float* lar    = (const float*)d_in[2];
    const float* aim    = (const float*)d_in[3];
    const float* Bp     = (const float*)d_in[4];
    const float* Cp     = (const float*)d_in[5];
    const float* Dp     = (const float*)d_in[6];
    float* out = (float*)d_out;

    int D   = in_sizes[6];              // D_param has D elements
    int BSZ = 4;                        // batch (fixed by problem)
    int L   = in_sizes[0] / (BSZ * D);
    int NCH = (L + TCHUNK - 1) / TCHUNK;

    dim3 blk(128);
    dim3 grd((D + 127) / 128, BSZ, NCH);

    s4d_pass1<<<grd, blk>>>(x, log_dt, lar, aim, L, D);

    int total2 = BSZ * NSTATE * D;
    s4d_pass2<<<(total2 + 255) / 256, 256>>>(log_dt, lar, aim, D, BSZ, NCH);

    s4d_pass3<<<grd, blk>>>(x, log_dt, lar, aim, Bp, Cp, Dp, out, L, D);
}

// round 2
// speedup vs baseline: 1.1495x; 1.1495x over previous
#include <cuda_runtime.h>

// S4D SSM layer, exact recurrence formulation of the FFT causal conv.
// y[l,b,d] = silu( Re(sum_n p_n s_n[l]) + x[l,b,d]*Dp[d] ),  s = q*s + x.
//
// 3-pass chunked scan, TCHUNK=128, time-unrolled with hoisted loads.

#define NSTATE 16
#define PACKS  8       // 2 states per f32x2 pack
#define TCHUNK 128     // must be power of two (pass2 squares log2(TCHUNK) times)
#define LOG2_TCHUNK 7
#define SCALE_F 0.25f  // sqrt(1/16)

typedef unsigned long long ull;

// f32x2 packed math (Blackwell sm_103a)
__device__ __forceinline__ ull pack2(float lo, float hi) {
    ull r; asm("mov.b64 %0, {%1,%2};" : "=l"(r) : "f"(lo), "f"(hi)); return r;
}
__device__ __forceinline__ void unpack2(ull v, float& a, float& b) {
    asm("mov.b64 {%0,%1}, %2;" : "=f"(a), "=f"(b) : "l"(v));
}
__device__ __forceinline__ ull fma2(ull a, ull b, ull c) {
    ull d; asm("fma.rn.f32x2 %0, %1, %2, %3;" : "=l"(d) : "l"(a), "l"(b), "l"(c)); return d;
}
__device__ __forceinline__ ull mul2(ull a, ull b) {
    ull d; asm("mul.rn.f32x2 %0, %1, %2;" : "=l"(d) : "l"(a), "l"(b)); return d;
}

// chunk-boundary states: layout ((c*BSZ + b)*NSTATE + n)*D + d   (coalesced in d)
__device__ float2 g_state[1 << 21];  // 16 MB scratch, static (allocation-free)

// Compute discretized q_n for feature d (bilinear transform).
__device__ __forceinline__ void compute_q(
    const float* __restrict__ log_dt, const float* __restrict__ log_A_real,
    const float* __restrict__ A_imag, int d,
    float* qr, float* qi, float* dt_out)
{
    float dt = __expf(log_dt[d]);
    *dt_out = dt;
#pragma unroll
    for (int n = 0; n < NSTATE; n++) {
        float zr = -0.5f * dt * __expf(log_A_real[d * NSTATE + n]);
        float zi =  0.5f * dt * A_imag[d * NSTATE + n];
        float omz = 1.0f - zr;
        float inv = __fdividef(1.0f, omz * omz + zi * zi);
        qr[n] = (1.0f - zr * zr - zi * zi) * inv;
        qi[n] = 2.0f * zi * inv;
    }
}

// one recurrence step over all packs
__device__ __forceinline__ void step_state(
    const ull* Qr, const ull* Qi, const ull* nQi, ull* Sr, ull* Sm, ull X2)
{
#pragma unroll
    for (int j = 0; j < PACKS; j++) {
        // sr' = qr*sr + qi*m + x   (m = -si)
        ull t   = fma2(Qi[j], Sm[j], X2);
        ull nsr = fma2(Qr[j], Sr[j], t);
        // m'  = -qi*sr + qr*m
        ull nm  = fma2(nQi[j], Sr[j], mul2(Qr[j], Sm[j]));
        Sr[j] = nsr; Sm[j] = nm;
    }
}

__global__ void __launch_bounds__(128) s4d_pass1(
    const float* __restrict__ x, const float* __restrict__ log_dt,
    const float* __restrict__ log_A_real, const float* __restrict__ A_imag,
    int L, int D)
{
    int d = blockIdx.x * blockDim.x + threadIdx.x;
    if (d >= D) return;
    int b = blockIdx.y;
    int c = blockIdx.z;
    int BSZ = gridDim.y;

    float qr[NSTATE], qi[NSTATE], dt;
    compute_q(log_dt, log_A_real, A_imag, d, qr, qi, &dt);

    ull Qr[PACKS], Qi[PACKS], nQi[PACKS], Sr[PACKS], Sm[PACKS];
#pragma unroll
    for (int j = 0; j < PACKS; j++) {
        Qr[j]  = pack2(qr[2*j],  qr[2*j+1]);
        Qi[j]  = pack2(qi[2*j],  qi[2*j+1]);
        nQi[j] = pack2(-qi[2*j], -qi[2*j+1]);
        Sr[j] = 0ull; Sm[j] = 0ull;   // state; Sm holds m = -si
    }

    int l0 = c * TCHUNK;
    const float* xp = x + ((long long)l0 * BSZ + b) * D + d;
    long long xstride = (long long)BSZ * D;

    // TCHUNK is a multiple of 4; unroll x4 with hoisted loads (MLP=4)
    for (int l = 0; l < TCHUNK; l += 4) {
        float x0 = xp[0];
        float x1 = xp[xstride];
        float x2 = xp[2 * xstride];
        float x3 = xp[3 * xstride];
        xp += 4 * xstride;
        step_state(Qr, Qi, nQi, Sr, Sm, pack2(x0, x0));
        step_state(Qr, Qi, nQi, Sr, Sm, pack2(x1, x1));
        step_state(Qr, Qi, nQi, Sr, Sm, pack2(x2, x2));
        step_state(Qr, Qi, nQi, Sr, Sm, pack2(x3, x3));
    }

    float2* st = g_state + (((long long)c * BSZ + b) * NSTATE) * D + d;
#pragma unroll
    for (int j = 0; j < PACKS; j++) {
        float r0, r1, m0, m1;
        unpack2(Sr[j], r0, r1); unpack2(Sm[j], m0, m1);
        st[(2*j    ) * D] = make_float2(r0, -m0);  // store (sr, si)
        st[(2*j + 1) * D] = make_float2(r1, -m1);
    }
}

__global__ void s4d_pass2(
    const float* __restrict__ log_dt, const float* __restrict__ log_A_real,
    const float* __restrict__ A_imag, int D, int BSZ, int NCH)
{
    int id = blockIdx.x * blockDim.x + threadIdx.x;
    int total = BSZ * NSTATE * D;
    if (id >= total) return;
    int d = id % D;
    int n = (id / D) % NSTATE;
    int b = id / (D * NSTATE);

    float dt = __expf(log_dt[d]);
    float zr = -0.5f * dt * __expf(log_A_real[d * NSTATE + n]);
    float zi =  0.5f * dt * A_imag[d * NSTATE + n];
    float omz = 1.0f - zr;
    float inv = __fdividef(1.0f, omz * omz + zi * zi);
    float qr = (1.0f - zr * zr - zi * zi) * inv;
    float qi = 2.0f * zi * inv;

    // q^TCHUNK via repeated squaring (TCHUNK = 2^LOG2_TCHUNK)
#pragma unroll
    for (int i = 0; i < LOG2_TCHUNK; i++) {
        float nr = qr * qr - qi * qi;
        float ni = 2.0f * qr * qi;
        qr = nr; qi = ni;
    }

    long long base    = ((long long)b * NSTATE + n) * D + d;
    long long cstride = (long long)BSZ * NSTATE * D;
    float2 s = g_state[base];
    for (int c = 1; c < NCH; c++) {
        float2 t = g_state[base + (long long)c * cstride];
        float nr = qr * s.x - qi * s.y + t.x;
        float ni = qr * s.y + qi * s.x + t.y;
        s.x = nr; s.y = ni;
        g_state[base + (long long)c * cstride] = s;
    }
}

__global__ void __launch_bounds__(128) s4d_pass3(
    const float* __restrict__ x, const float* __restrict__ log_dt,
    const float* __restrict__ log_A_real, const float* __restrict__ A_imag,
    const float* __restrict__ Bparam, const float* __restrict__ Cparam,
    const float* __restrict__ Dparam, float* __restrict__ out,
    int L, int D)
{
    int d = blockIdx.x * blockDim.x + threadIdx.x;
    if (d >= D) return;
    int b = blockIdx.y;
    int c = blockIdx.z;
    int BSZ = gridDim.y;

    float qr[NSTATE], qi[NSTATE], dt;
    compute_q(log_dt, log_A_real, A_imag, d, qr, qi, &dt);

    ull Qr[PACKS], Qi[PACKS], nQi[PACKS], Pr[PACKS], Pi[PACKS], Sr[PACKS], Sm[PACKS];
#pragma unroll
    for (int j = 0; j < PACKS; j++) {
        float prj[2], pij[2];
#pragma unroll
        for (int k = 0; k < 2; k++) {
            int n = 2 * j + k;
            float zr = -0.5f * dt * __expf(log_A_real[d * NSTATE + n]);
            float zi =  0.5f * dt * A_imag[d * NSTATE + n];
            float omz = 1.0f - zr;
            float inv = __fdividef(1.0f, omz * omz + zi * zi);
            float Br = Bparam[(d * NSTATE + n) * 2 + 0];
            float Bi = Bparam[(d * NSTATE + n) * 2 + 1];
            float Cr = Cparam[(d * NSTATE + n) * 2 + 0];
            float Ci = Cparam[(d * NSTATE + n) * 2 + 1];
            float ccr = Br * Cr - Bi * Ci;
            float cci = Br * Ci + Bi * Cr;
            float w = dt * SCALE_F * inv;
            prj[k] = w * (ccr * omz - cci * zi);
            pij[k] = w * (ccr * zi + cci * omz);
        }
        Qr[j]  = pack2(qr[2*j],  qr[2*j+1]);
        Qi[j]  = pack2(qi[2*j],  qi[2*j+1]);
        nQi[j] = pack2(-qi[2*j], -qi[2*j+1]);
        Pr[j]  = pack2(prj[0], prj[1]);
        Pi[j]  = pack2(pij[0], pij[1]);
        Sr[j] = 0ull; Sm[j] = 0ull;
    }

    // true incoming state = end state of chunk c-1
    if (c > 0) {
        const float2* st = g_state + (((long long)(c - 1) * BSZ + b) * NSTATE) * D + d;
#pragma unroll
        for (int j = 0; j < PACKS; j++) {
            float2 v0 = st[(2*j    ) * D];
            float2 v1 = st[(2*j + 1) * D];
            Sr[j] = pack2(v0.x, v1.x);
            Sm[j] = pack2(-v0.y, -v1.y);  // m = -si
        }
    }

    float dpar = Dparam[d];
    int l0 = c * TCHUNK;
    const float* xp = x + ((long long)l0 * BSZ + b) * D + d;
    float* op = out + ((long long)l0 * BSZ + b) * D + d;
    long long xstride = (long long)BSZ * D;

    // unroll x2 with hoisted loads
    for (int l = 0; l < TCHUNK; l += 2) {
        float xv0 = xp[0];
        float xv1 = xp[xstride];
        xp += 2 * xstride;

#pragma unroll
        for (int u = 0; u < 2; u++) {
            float xv = (u == 0) ? xv0 : xv1;
            ull X2 = pack2(xv, xv);
            ull acc0 = 0ull, acc1 = 0ull;
#pragma unroll
            for (int j = 0; j < PACKS; j++) {
                ull t   = fma2(Qi[j], Sm[j], X2);
                ull nsr = fma2(Qr[j], Sr[j], t);
                ull nm  = fma2(nQi[j], Sr[j], mul2(Qr[j], Sm[j]));
                Sr[j] = nsr; Sm[j] = nm;
                // y += pr*sr' + pi*m'   (= pr*sr - pi*si)
                if (j & 1) {
                    acc1 = fma2(Pi[j], nm, acc1);
                    acc1 = fma2(Pr[j], nsr, acc1);
                } else {
                    acc0 = fma2(Pi[j], nm, acc0);
                    acc0 = fma2(Pr[j], nsr, acc0);
                }
            }
            float a0, a1, b0, b1;
            unpack2(acc0, a0, a1); unpack2(acc1, b0, b1);
            float y = (a0 + a1) + (b0 + b1);
            float z = fmaf(xv, dpar, y);
            float sg = __fdividef(1.0f, 1.0f + __expf(-z));
            op[(long long)u * xstride] = z * sg;
        }
        op += 2 * xstride;
    }
}

extern "C" void kernel_launch(void* const* d_in, const int* in_sizes, int n_in,
                              void* d_out, int out_size)
{
    const float* x      = (const float*)d_in[0];
    const float* log_dt = (const float*)d_in[1];
    const float* lar    = (const float*)d_in[2];
    const float* aim    = (const float*)d_in[3];
    const float* Bp     = (const float*)d_in[4];
    const float* Cp     = (const float*)d_in[5];
    const float* Dp     = (const float*)d_in[6];
    float* out = (float*)d_out;

    int D   = in_sizes[6];              // D_param has D elements
    int BSZ = 4;                        // batch (fixed by problem)
    int L   = in_sizes[0] / (BSZ * D);
    int NCH = (L + TCHUNK - 1) / TCHUNK;

    dim3 blk(128);
    dim3 grd((D + 127) / 128, BSZ, NCH);

    s4d_pass1<<<grd, blk>>>(x, log_dt, lar, aim, L, D);

    int total2 = BSZ * NSTATE * D;
    s4d_pass2<<<(total2 + 255) / 256, 256>>>(log_dt, lar, aim, D, BSZ, NCH);

    s4d_pass3<<<grd, blk>>>(x, log_dt, lar, aim, Bp, Cp, Dp, out, L, D);
}